// round 12
// baseline (speedup 1.0000x reference)
#include <cuda_runtime.h>
#include <cuda_fp16.h>
#include <cuda_bf16.h>
#include <mma.h>
#include <math.h>

using namespace nvcuda;

#define N_NODES 50000
#define N_EDGES 800000
#define IN_DIM  128
#define HID_DIM 128
#define OUT_DIM 64

typedef unsigned long long ull;

// ---------------- scratch (static device globals; no allocation) ----------------
__device__ float  g_dinv[N_NODES];
__device__ int    g_degi[N_NODES];
__device__ int    g_off [N_NODES + 1];
__device__ int    g_cur [N_NODES];
__device__ int    g_bsum[256];
__device__ int    g_col [N_EDGES];
__device__ __half g_hh  [(size_t)N_NODES * HID_DIM];  // x @ W1 (raw, fp16 gather copy)
__device__ __half g_h2h [(size_t)N_NODES * OUT_DIM];  // h1 @ W2 (raw, fp16 gather copy)

// ---------------- degree / norm / CSR build ----------------
__global__ void k_zero() {
    int i = blockIdx.x * blockDim.x + threadIdx.x;
    if (i < N_NODES) g_degi[i] = 0;
}
__global__ void k_count(const int* __restrict__ dst) {
    int e = blockIdx.x * blockDim.x + threadIdx.x;
    if (e < N_EDGES) atomicAdd(&g_degi[dst[e]], 1);
}
__global__ void k_scan1() {
    __shared__ int s[256];
    int i = blockIdx.x * 256 + threadIdx.x;
    int v = (i < N_NODES) ? g_degi[i] : 0;
    if (i < N_NODES) g_dinv[i] = rsqrtf((float)(v + 1));  // +1 self-loop
    s[threadIdx.x] = v;
    __syncthreads();
    for (int d = 1; d < 256; d <<= 1) {
        int t = (threadIdx.x >= d) ? s[threadIdx.x - d] : 0;
        __syncthreads();
        s[threadIdx.x] += t;
        __syncthreads();
    }
    if (i < N_NODES) g_off[i] = s[threadIdx.x] - v;
    if (threadIdx.x == 255) g_bsum[blockIdx.x] = s[255];
}
__global__ void k_scan2(int nblk) {
    __shared__ int s[256];
    int t = threadIdx.x;
    int v = (t < nblk) ? g_bsum[t] : 0;
    s[t] = v;
    __syncthreads();
    for (int d = 1; d < 256; d <<= 1) {
        int u = (t >= d) ? s[t - d] : 0;
        __syncthreads();
        s[t] += u;
        __syncthreads();
    }
    if (t < nblk) g_bsum[t] = s[t] - v;
}
__global__ void k_scan3() {
    int i = blockIdx.x * blockDim.x + threadIdx.x;
    if (i < N_NODES) {
        int o = g_off[i] + g_bsum[i >> 8];
        g_off[i] = o;
        g_cur[i] = o;
    }
    if (i == 0) g_off[N_NODES] = N_EDGES;
}
__global__ void k_fill(const int* __restrict__ src, const int* __restrict__ dst) {
    int e = blockIdx.x * blockDim.x + threadIdx.x;
    if (e < N_EDGES) {
        int p = atomicAdd(&g_cur[dst[e]], 1);
        g_col[p] = src[e];
    }
}

// ---------------- split-bf16 helper ----------------
__device__ __forceinline__ void split_bf16(float v, __nv_bfloat16& h, __nv_bfloat16& l) {
    h = __float2bfloat16(v);
    l = __float2bfloat16(v - __bfloat162float(h));
}

// ---------------- GEMM via split-bf16 WMMA (fp32-grade accuracy) ----------------
// Block: 256 threads = 8 warps, arranged WM x WN (WM*WN==8). Tile: MT=WM*16 rows x N cols.
// Y = X[.,K] @ W[K,N], written as fp16.
template <int K, int N, int WM, int WN>
__global__ void k_gemm_wmma(const float* __restrict__ X, const float* __restrict__ W,
                            __half* __restrict__ Y) {
    constexpr int MT = WM * 16;
    constexpr int NF = N / (WN * 16);   // n-fragments per warp
    __shared__ __nv_bfloat16 Ah[MT * 16], Al[MT * 16];   // A tile, ld=16
    __shared__ __nv_bfloat16 Bh[16 * N],  Bl[16 * N];    // B tile, ld=N
    __shared__ float Cst[MT * N];

    const int tid = threadIdx.x;
    const int wi  = tid >> 5;
    const int wm  = wi % WM;            // warp row
    const int wn  = wi / WM;            // warp col
    const long r0 = (long)blockIdx.x * MT;
    const int colbase = wn * (N / WN);

    wmma::fragment<wmma::accumulator, 16, 16, 16, float> acc[NF];
#pragma unroll
    for (int f = 0; f < NF; f++) wmma::fill_fragment(acc[f], 0.0f);

    for (int k0 = 0; k0 < K; k0 += 16) {
        // load + split A tile (MT x 16)
        for (int idx = tid; idx < MT * 16; idx += 256) {
            int r = idx >> 4, c = idx & 15;
            long row = r0 + r; if (row >= N_NODES) row = N_NODES - 1;
            float v = __ldg(X + row * K + k0 + c);
            split_bf16(v, Ah[idx], Al[idx]);
        }
        // load + split B tile (16 x N)
        for (int idx = tid; idx < 16 * N; idx += 256) {
            int r = idx / N, c = idx % N;
            float v = __ldg(W + (size_t)(k0 + r) * N + c);
            split_bf16(v, Bh[idx], Bl[idx]);
        }
        __syncthreads();

        wmma::fragment<wmma::matrix_a, 16, 16, 16, __nv_bfloat16, wmma::row_major> a_h, a_l;
        wmma::load_matrix_sync(a_h, Ah + wm * 16 * 16, 16);
        wmma::load_matrix_sync(a_l, Al + wm * 16 * 16, 16);
#pragma unroll
        for (int f = 0; f < NF; f++) {
            wmma::fragment<wmma::matrix_b, 16, 16, 16, __nv_bfloat16, wmma::row_major> b_h, b_l;
            int cb = colbase + f * 16;
            wmma::load_matrix_sync(b_h, Bh + cb, N);
            wmma::load_matrix_sync(b_l, Bl + cb, N);
            wmma::mma_sync(acc[f], a_h, b_h, acc[f]);
            wmma::mma_sync(acc[f], a_l, b_h, acc[f]);
            wmma::mma_sync(acc[f], a_h, b_l, acc[f]);
        }
        __syncthreads();
    }

    // stage to smem, then guarded fp16 write
#pragma unroll
    for (int f = 0; f < NF; f++)
        wmma::store_matrix_sync(Cst + (size_t)(wm * 16) * N + colbase + f * 16,
                                acc[f], N, wmma::mem_row_major);
    __syncthreads();

    for (int idx = tid; idx < MT * N / 2; idx += 256) {
        int row = idx / (N / 2);
        int c2  = idx % (N / 2);
        long grow = r0 + row;
        if (grow < N_NODES) {
            float2 fv = *(const float2*)&Cst[(size_t)row * N + 2 * c2];
            *(__half2*)&Y[grow * N + 2 * c2] = __floats2half2_rn(fv.x, fv.y);
        }
    }
}

// ---------------- pull aggregation, C=128: fp16 gather, fp32 accumulate ----------
__global__ void k_pull128(const __half* __restrict__ hraw, const float* __restrict__ b,
                          float* __restrict__ out) {
    int w = (blockIdx.x * blockDim.x + threadIdx.x) >> 5;
    if (w >= N_NODES) return;
    int lane = threadIdx.x & 31;
    float din = g_dinv[w];
    uint2 hr = __ldg((const uint2*)(hraw + (size_t)w * 128) + lane);
    float2 h0a = __half22float2(*(__half2*)&hr.x);
    float2 h0b = __half22float2(*(__half2*)&hr.y);
    float4 bv = __ldg((const float4*)b + lane);
    float sl = din * din;
    float4 acc, acc2 = make_float4(0.f, 0.f, 0.f, 0.f);
    acc.x = fmaf(h0a.x, sl, bv.x); acc.y = fmaf(h0a.y, sl, bv.y);
    acc.z = fmaf(h0b.x, sl, bv.z); acc.w = fmaf(h0b.y, sl, bv.w);

    int s0 = g_off[w], s1 = g_off[w + 1];
    for (int j0 = s0; j0 < s1; j0 += 32) {
        int jj = j0 + lane;
        int cc = 0; float nd = 0.0f;
        if (jj < s1) { cc = g_col[jj]; nd = g_dinv[cc]; }
        int cnt = min(32, s1 - j0);
        int i = 0;
        for (; i + 2 <= cnt; i += 2) {
            int   sA = __shfl_sync(0xffffffffu, cc, i);
            float nA = __shfl_sync(0xffffffffu, nd, i) * din;
            int   sB = __shfl_sync(0xffffffffu, cc, i + 1);
            float nB = __shfl_sync(0xffffffffu, nd, i + 1) * din;
            uint2 rA = __ldg((const uint2*)(hraw + (size_t)sA * 128) + lane);
            uint2 rB = __ldg((const uint2*)(hraw + (size_t)sB * 128) + lane);
            float2 a0 = __half22float2(*(__half2*)&rA.x);
            float2 a1 = __half22float2(*(__half2*)&rA.y);
            float2 b0 = __half22float2(*(__half2*)&rB.x);
            float2 b1 = __half22float2(*(__half2*)&rB.y);
            acc.x  = fmaf(a0.x, nA, acc.x);  acc.y  = fmaf(a0.y, nA, acc.y);
            acc.z  = fmaf(a1.x, nA, acc.z);  acc.w  = fmaf(a1.y, nA, acc.w);
            acc2.x = fmaf(b0.x, nB, acc2.x); acc2.y = fmaf(b0.y, nB, acc2.y);
            acc2.z = fmaf(b1.x, nB, acc2.z); acc2.w = fmaf(b1.y, nB, acc2.w);
        }
        if (i < cnt) {
            int   sA = __shfl_sync(0xffffffffu, cc, i);
            float nA = __shfl_sync(0xffffffffu, nd, i) * din;
            uint2 rA = __ldg((const uint2*)(hraw + (size_t)sA * 128) + lane);
            float2 a0 = __half22float2(*(__half2*)&rA.x);
            float2 a1 = __half22float2(*(__half2*)&rA.y);
            acc.x = fmaf(a0.x, nA, acc.x); acc.y = fmaf(a0.y, nA, acc.y);
            acc.z = fmaf(a1.x, nA, acc.z); acc.w = fmaf(a1.y, nA, acc.w);
        }
    }
    acc.x = fmaxf(acc.x + acc2.x, 0.0f); acc.y = fmaxf(acc.y + acc2.y, 0.0f);
    acc.z = fmaxf(acc.z + acc2.z, 0.0f); acc.w = fmaxf(acc.w + acc2.w, 0.0f);
    ((float4*)(out + (size_t)w * 128))[lane] = acc;
}

// ---------------- pull aggregation, C=64: fp16 gather, fp32 accumulate -----------
__global__ void k_pull64(const __half* __restrict__ hraw, const float* __restrict__ b,
                         float* __restrict__ out) {
    int w = (blockIdx.x * blockDim.x + threadIdx.x) >> 5;
    if (w >= N_NODES) return;
    int lane = threadIdx.x & 31;
    float din = g_dinv[w];
    unsigned hr = __ldg((const unsigned*)(hraw + (size_t)w * 64) + lane);
    float2 h0 = __half22float2(*(__half2*)&hr);
    float2 bv = __ldg((const float2*)b + lane);
    float sl = din * din;
    float2 acc, acc2 = make_float2(0.f, 0.f);
    acc.x = fmaf(h0.x, sl, bv.x); acc.y = fmaf(h0.y, sl, bv.y);

    int s0 = g_off[w], s1 = g_off[w + 1];
    for (int j0 = s0; j0 < s1; j0 += 32) {
        int jj = j0 + lane;
        int cc = 0; float nd = 0.0f;
        if (jj < s1) { cc = g_col[jj]; nd = g_dinv[cc]; }
        int cnt = min(32, s1 - j0);
        int i = 0;
        for (; i + 2 <= cnt; i += 2) {
            int   sA = __shfl_sync(0xffffffffu, cc, i);
            float nA = __shfl_sync(0xffffffffu, nd, i) * din;
            int   sB = __shfl_sync(0xffffffffu, cc, i + 1);
            float nB = __shfl_sync(0xffffffffu, nd, i + 1) * din;
            unsigned rA = __ldg((const unsigned*)(hraw + (size_t)sA * 64) + lane);
            unsigned rB = __ldg((const unsigned*)(hraw + (size_t)sB * 64) + lane);
            float2 fA = __half22float2(*(__half2*)&rA);
            float2 fB = __half22float2(*(__half2*)&rB);
            acc.x  = fmaf(fA.x, nA, acc.x);  acc.y  = fmaf(fA.y, nA, acc.y);
            acc2.x = fmaf(fB.x, nB, acc2.x); acc2.y = fmaf(fB.y, nB, acc2.y);
        }
        if (i < cnt) {
            int   sA = __shfl_sync(0xffffffffu, cc, i);
            float nA = __shfl_sync(0xffffffffu, nd, i) * din;
            unsigned rA = __ldg((const unsigned*)(hraw + (size_t)sA * 64) + lane);
            float2 fA = __half22float2(*(__half2*)&rA);
            acc.x = fmaf(fA.x, nA, acc.x); acc.y = fmaf(fA.y, nA, acc.y);
        }
    }
    acc.x += acc2.x; acc.y += acc2.y;
    ((float2*)(out + (size_t)w * 64))[lane] = acc;
}

// ---------------- launch: R10 structure (CSR ∥ GEMM1), WMMA GEMMs ---------------
extern "C" void kernel_launch(void* const* d_in, const int* in_sizes, int n_in,
                              void* d_out, int out_size) {
    const float* x  = (const float*)d_in[0];
    const int*   ei = (const int*)  d_in[1];
    const float* W1 = (const float*)d_in[2];
    const float* b1 = (const float*)d_in[3];
    const float* W2 = (const float*)d_in[4];
    const float* b2 = (const float*)d_in[5];

    const int* src = ei;
    const int* dst = ei + N_EDGES;

    float* out_h2 = (float*)d_out;                       // [N, 64]
    float* out_h1 = out_h2 + (size_t)N_NODES * OUT_DIM;  // [N, 128]

    void *p_hh, *p_h2h;
    cudaGetSymbolAddress(&p_hh,  g_hh);
    cudaGetSymbolAddress(&p_h2h, g_h2h);
    __half* hhbuf  = (__half*)p_hh;
    __half* h2hbuf = (__half*)p_h2h;

    // lazy stream/event creation (first, non-captured, call only)
    static cudaStream_t s2 = nullptr;
    static cudaEvent_t  evFork = nullptr, evJoin = nullptr;
    if (s2 == nullptr) {
        cudaStreamCreateWithFlags(&s2, cudaStreamNonBlocking);
        cudaEventCreateWithFlags(&evFork, cudaEventDisableTiming);
        cudaEventCreateWithFlags(&evJoin, cudaEventDisableTiming);
    }

    const int TB = 256;
    const int nblk_nodes = (N_NODES + TB - 1) / TB;      // 196
    const int nblk_edges = (N_EDGES + TB - 1) / TB;

    // fork: s2 builds CSR while stream 0 runs GEMM1
    cudaEventRecord(evFork, 0);
    cudaStreamWaitEvent(s2, evFork, 0);

    // --- stream 0: GEMM1 (split-bf16 WMMA) -> fp16 hbuf ---
    // WM=4, WN=2: tile 64 rows x 128 cols
    k_gemm_wmma<IN_DIM, HID_DIM, 4, 2><<<(N_NODES + 63) / 64, 256>>>(x, W1, hhbuf);

    // --- stream s2: degree + CSR build ---
    k_zero <<<nblk_nodes, TB, 0, s2>>>();
    k_count<<<nblk_edges, TB, 0, s2>>>(dst);
    k_scan1<<<nblk_nodes, TB, 0, s2>>>();
    k_scan2<<<1,          TB, 0, s2>>>(nblk_nodes);
    k_scan3<<<nblk_nodes, TB, 0, s2>>>();
    k_fill <<<nblk_edges, TB, 0, s2>>>(src, dst);

    // join: stream 0 waits for CSR before the pulls
    cudaEventRecord(evJoin, s2);
    cudaStreamWaitEvent(0, evJoin, 0);

    // --- stream 0: pull1 (fp16 gather) -> GEMM2 (WMMA) -> pull2 (fp16 gather) ---
    k_pull128<<<(N_NODES * 32 + TB - 1) / TB, TB>>>(hhbuf, b1, out_h1);
    // WM=8, WN=1: tile 128 rows x 64 cols
    k_gemm_wmma<HID_DIM, OUT_DIM, 8, 1><<<(N_NODES + 127) / 128, 256>>>(out_h1, W2, h2hbuf);
    k_pull64<<<(N_NODES * 32 + TB - 1) / TB, TB>>>(h2hbuf, b2, out_h2);
}

// round 13
// speedup vs baseline: 1.3787x; 1.3787x over previous
#include <cuda_runtime.h>
#include <cuda_fp16.h>
#include <math.h>

#define N_NODES 50000
#define N_EDGES 800000
#define IN_DIM  128
#define HID_DIM 128
#define OUT_DIM 64

typedef unsigned long long ull;

// ---------------- scratch (static device globals; no allocation) ----------------
__device__ float  g_dinv[N_NODES];
__device__ int    g_degi[N_NODES];
__device__ int    g_off [N_NODES + 1];
__device__ int    g_cur [N_NODES];
__device__ int    g_bsum[256];
__device__ int    g_col [N_EDGES];
__device__ __half g_hh  [(size_t)N_NODES * HID_DIM];
__device__ __half g_h2h [(size_t)N_NODES * OUT_DIM];

// ---------------- f32x2 packed math ----------------
__device__ __forceinline__ ull pack2(float lo, float hi) {
    ull r; asm("mov.b64 %0, {%1, %2};" : "=l"(r) : "f"(lo), "f"(hi)); return r;
}
__device__ __forceinline__ ull fma2(ull a, ull b, ull c) {
    ull d; asm("fma.rn.f32x2 %0, %1, %2, %3;" : "=l"(d) : "l"(a), "l"(b), "l"(c)); return d;
}
__device__ __forceinline__ float2 unpack2(ull p) {
    float2 f; asm("mov.b64 {%0, %1}, %2;" : "=f"(f.x), "=f"(f.y) : "l"(p)); return f;
}

// ---------------- degree / norm / CSR build ----------------
__global__ void k_zero() {
    int i = blockIdx.x * blockDim.x + threadIdx.x;
    if (i < N_NODES) g_degi[i] = 0;
}
__global__ void k_count(const int* __restrict__ dst) {
    int e = blockIdx.x * blockDim.x + threadIdx.x;
    if (e < N_EDGES) atomicAdd(&g_degi[dst[e]], 1);
}
__global__ void k_scan1() {
    __shared__ int s[256];
    int i = blockIdx.x * 256 + threadIdx.x;
    int v = (i < N_NODES) ? g_degi[i] : 0;
    if (i < N_NODES) g_dinv[i] = rsqrtf((float)(v + 1));  // +1 self-loop
    s[threadIdx.x] = v;
    __syncthreads();
    for (int d = 1; d < 256; d <<= 1) {
        int t = (threadIdx.x >= d) ? s[threadIdx.x - d] : 0;
        __syncthreads();
        s[threadIdx.x] += t;
        __syncthreads();
    }
    if (i < N_NODES) g_off[i] = s[threadIdx.x] - v;
    if (threadIdx.x == 255) g_bsum[blockIdx.x] = s[255];
}
__global__ void k_scan2(int nblk) {
    __shared__ int s[256];
    int t = threadIdx.x;
    int v = (t < nblk) ? g_bsum[t] : 0;
    s[t] = v;
    __syncthreads();
    for (int d = 1; d < 256; d <<= 1) {
        int u = (t >= d) ? s[t - d] : 0;
        __syncthreads();
        s[t] += u;
        __syncthreads();
    }
    if (t < nblk) g_bsum[t] = s[t] - v;
}
__global__ void k_scan3() {
    int i = blockIdx.x * blockDim.x + threadIdx.x;
    if (i < N_NODES) {
        int o = g_off[i] + g_bsum[i >> 8];
        g_off[i] = o;
        g_cur[i] = o;
    }
    if (i == 0) g_off[N_NODES] = N_EDGES;
}
__global__ void k_fill(const int* __restrict__ src, const int* __restrict__ dst) {
    int e = blockIdx.x * blockDim.x + threadIdx.x;
    if (e < N_EDGES) {
        int p = atomicAdd(&g_cur[dst[e]], 1);
        g_col[p] = src[e];
    }
}

// ---------------- GEMM (measured-best f32x2 microtile), fp16 output -------------
template <int K, int N, int RB, int TY>
__global__ void k_gemm(const float* __restrict__ X, const float* __restrict__ W,
                       __half* __restrict__ Y) {
    constexpr int CP = N / 32;
    constexpr int T  = TY * 16;
    __shared__ float xs[RB * 33];
    __shared__ float ws[32 * N];
    const int tid = threadIdx.x;
    const int tx = tid & 15, ty = tid >> 4;
    const long r0 = (long)blockIdx.x * RB;

    ull acc[8][CP];
#pragma unroll
    for (int r = 0; r < 8; r++)
#pragma unroll
        for (int c = 0; c < CP; c++) acc[r][c] = 0ull;

    for (int k0 = 0; k0 < K; k0 += 32) {
        for (int t = tid; t < RB * 8; t += T) {
            int r = t >> 3, q = t & 7;
            long row = r0 + r; if (row >= N_NODES) row = N_NODES - 1;
            float4 v = __ldg((const float4*)(X + row * K + k0) + q);
            float* xp = &xs[r * 33 + q * 4];
            xp[0] = v.x; xp[1] = v.y; xp[2] = v.z; xp[3] = v.w;
        }
        const float4* wsrc = (const float4*)(W + (size_t)k0 * N);
        for (int t = tid; t < 8 * N; t += T)
            ((float4*)ws)[t] = __ldg(wsrc + t);
        __syncthreads();

#pragma unroll 8
        for (int kk = 0; kk < 32; kk++) {
            ull wv[CP];
#pragma unroll
            for (int c = 0; c < CP; c++)
                wv[c] = *(const ull*)&ws[kk * N + 2 * tx + 32 * c];
#pragma unroll
            for (int r = 0; r < 8; r++) {
                float xv = xs[(ty * 8 + r) * 33 + kk];
                ull xx = pack2(xv, xv);
#pragma unroll
                for (int c = 0; c < CP; c++) acc[r][c] = fma2(xx, wv[c], acc[r][c]);
            }
        }
        __syncthreads();
    }

#pragma unroll
    for (int r = 0; r < 8; r++) {
        long row = r0 + ty * 8 + r;
        if (row < N_NODES) {
#pragma unroll
            for (int c = 0; c < CP; c++) {
                float2 f = unpack2(acc[r][c]);
                *(__half2*)&Y[row * N + 2 * tx + 32 * c] = __floats2half2_rn(f.x, f.y);
            }
        }
    }
}

// ---------------- pull aggregation, C=128: fp16 gather, 4-way pipelined ----------
__global__ void k_pull128(const __half* __restrict__ hraw, const float* __restrict__ b,
                          float* __restrict__ out) {
    int w = (blockIdx.x * blockDim.x + threadIdx.x) >> 5;
    if (w >= N_NODES) return;
    int lane = threadIdx.x & 31;
    float din = g_dinv[w];
    uint2 hr = __ldg((const uint2*)(hraw + (size_t)w * 128) + lane);
    float2 h0a = __half22float2(*(__half2*)&hr.x);
    float2 h0b = __half22float2(*(__half2*)&hr.y);
    float4 bv = __ldg((const float4*)b + lane);
    float sl = din * din;
    float4 a0 = make_float4(fmaf(h0a.x, sl, bv.x), fmaf(h0a.y, sl, bv.y),
                            fmaf(h0b.x, sl, bv.z), fmaf(h0b.y, sl, bv.w));
    float4 a1 = make_float4(0.f, 0.f, 0.f, 0.f);
    float4 a2 = make_float4(0.f, 0.f, 0.f, 0.f);
    float4 a3 = make_float4(0.f, 0.f, 0.f, 0.f);

    int s0 = g_off[w], s1 = g_off[w + 1];
    for (int j0 = s0; j0 < s1; j0 += 32) {
        int jj = j0 + lane;
        int cc = 0; float nd = 0.0f;
        if (jj < s1) { cc = g_col[jj]; nd = g_dinv[cc]; }
        int cnt = min(32, s1 - j0);
        int i = 0;
        for (; i + 4 <= cnt; i += 4) {
            int   sA = __shfl_sync(0xffffffffu, cc, i);
            int   sB = __shfl_sync(0xffffffffu, cc, i + 1);
            int   sC = __shfl_sync(0xffffffffu, cc, i + 2);
            int   sD = __shfl_sync(0xffffffffu, cc, i + 3);
            float nA = __shfl_sync(0xffffffffu, nd, i)     * din;
            float nB = __shfl_sync(0xffffffffu, nd, i + 1) * din;
            float nC = __shfl_sync(0xffffffffu, nd, i + 2) * din;
            float nD = __shfl_sync(0xffffffffu, nd, i + 3) * din;
            uint2 rA = __ldg((const uint2*)(hraw + (size_t)sA * 128) + lane);
            uint2 rB = __ldg((const uint2*)(hraw + (size_t)sB * 128) + lane);
            uint2 rC = __ldg((const uint2*)(hraw + (size_t)sC * 128) + lane);
            uint2 rD = __ldg((const uint2*)(hraw + (size_t)sD * 128) + lane);
            float2 fA0 = __half22float2(*(__half2*)&rA.x), fA1 = __half22float2(*(__half2*)&rA.y);
            float2 fB0 = __half22float2(*(__half2*)&rB.x), fB1 = __half22float2(*(__half2*)&rB.y);
            float2 fC0 = __half22float2(*(__half2*)&rC.x), fC1 = __half22float2(*(__half2*)&rC.y);
            float2 fD0 = __half22float2(*(__half2*)&rD.x), fD1 = __half22float2(*(__half2*)&rD.y);
            a0.x = fmaf(fA0.x, nA, a0.x); a0.y = fmaf(fA0.y, nA, a0.y);
            a0.z = fmaf(fA1.x, nA, a0.z); a0.w = fmaf(fA1.y, nA, a0.w);
            a1.x = fmaf(fB0.x, nB, a1.x); a1.y = fmaf(fB0.y, nB, a1.y);
            a1.z = fmaf(fB1.x, nB, a1.z); a1.w = fmaf(fB1.y, nB, a1.w);
            a2.x = fmaf(fC0.x, nC, a2.x); a2.y = fmaf(fC0.y, nC, a2.y);
            a2.z = fmaf(fC1.x, nC, a2.z); a2.w = fmaf(fC1.y, nC, a2.w);
            a3.x = fmaf(fD0.x, nD, a3.x); a3.y = fmaf(fD0.y, nD, a3.y);
            a3.z = fmaf(fD1.x, nD, a3.z); a3.w = fmaf(fD1.y, nD, a3.w);
        }
        for (; i < cnt; i++) {
            int   sA = __shfl_sync(0xffffffffu, cc, i);
            float nA = __shfl_sync(0xffffffffu, nd, i) * din;
            uint2 rA = __ldg((const uint2*)(hraw + (size_t)sA * 128) + lane);
            float2 fA0 = __half22float2(*(__half2*)&rA.x), fA1 = __half22float2(*(__half2*)&rA.y);
            a0.x = fmaf(fA0.x, nA, a0.x); a0.y = fmaf(fA0.y, nA, a0.y);
            a0.z = fmaf(fA1.x, nA, a0.z); a0.w = fmaf(fA1.y, nA, a0.w);
        }
    }
    float4 acc;
    acc.x = fmaxf(a0.x + a1.x + a2.x + a3.x, 0.0f);
    acc.y = fmaxf(a0.y + a1.y + a2.y + a3.y, 0.0f);
    acc.z = fmaxf(a0.z + a1.z + a2.z + a3.z, 0.0f);
    acc.w = fmaxf(a0.w + a1.w + a2.w + a3.w, 0.0f);
    ((float4*)(out + (size_t)w * 128))[lane] = acc;
}

// ---------------- pull aggregation, C=64: fp16 gather, 4-way pipelined -----------
__global__ void k_pull64(const __half* __restrict__ hraw, const float* __restrict__ b,
                         float* __restrict__ out) {
    int w = (blockIdx.x * blockDim.x + threadIdx.x) >> 5;
    if (w >= N_NODES) return;
    int lane = threadIdx.x & 31;
    float din = g_dinv[w];
    unsigned hr = __ldg((const unsigned*)(hraw + (size_t)w * 64) + lane);
    float2 h0 = __half22float2(*(__half2*)&hr);
    float2 bv = __ldg((const float2*)b + lane);
    float sl = din * din;
    float2 a0 = make_float2(fmaf(h0.x, sl, bv.x), fmaf(h0.y, sl, bv.y));
    float2 a1 = make_float2(0.f, 0.f);
    float2 a2 = make_float2(0.f, 0.f);
    float2 a3 = make_float2(0.f, 0.f);

    int s0 = g_off[w], s1 = g_off[w + 1];
    for (int j0 = s0; j0 < s1; j0 += 32) {
        int jj = j0 + lane;
        int cc = 0; float nd = 0.0f;
        if (jj < s1) { cc = g_col[jj]; nd = g_dinv[cc]; }
        int cnt = min(32, s1 - j0);
        int i = 0;
        for (; i + 4 <= cnt; i += 4) {
            int   sA = __shfl_sync(0xffffffffu, cc, i);
            int   sB = __shfl_sync(0xffffffffu, cc, i + 1);
            int   sC = __shfl_sync(0xffffffffu, cc, i + 2);
            int   sD = __shfl_sync(0xffffffffu, cc, i + 3);
            float nA = __shfl_sync(0xffffffffu, nd, i)     * din;
            float nB = __shfl_sync(0xffffffffu, nd, i + 1) * din;
            float nC = __shfl_sync(0xffffffffu, nd, i + 2) * din;
            float nD = __shfl_sync(0xffffffffu, nd, i + 3) * din;
            unsigned rA = __ldg((const unsigned*)(hraw + (size_t)sA * 64) + lane);
            unsigned rB = __ldg((const unsigned*)(hraw + (size_t)sB * 64) + lane);
            unsigned rC = __ldg((const unsigned*)(hraw + (size_t)sC * 64) + lane);
            unsigned rD = __ldg((const unsigned*)(hraw + (size_t)sD * 64) + lane);
            float2 fA = __half22float2(*(__half2*)&rA);
            float2 fB = __half22float2(*(__half2*)&rB);
            float2 fC = __half22float2(*(__half2*)&rC);
            float2 fD = __half22float2(*(__half2*)&rD);
            a0.x = fmaf(fA.x, nA, a0.x); a0.y = fmaf(fA.y, nA, a0.y);
            a1.x = fmaf(fB.x, nB, a1.x); a1.y = fmaf(fB.y, nB, a1.y);
            a2.x = fmaf(fC.x, nC, a2.x); a2.y = fmaf(fC.y, nC, a2.y);
            a3.x = fmaf(fD.x, nD, a3.x); a3.y = fmaf(fD.y, nD, a3.y);
        }
        for (; i < cnt; i++) {
            int   sA = __shfl_sync(0xffffffffu, cc, i);
            float nA = __shfl_sync(0xffffffffu, nd, i) * din;
            unsigned rA = __ldg((const unsigned*)(hraw + (size_t)sA * 64) + lane);
            float2 fA = __half22float2(*(__half2*)&rA);
            a0.x = fmaf(fA.x, nA, a0.x); a0.y = fmaf(fA.y, nA, a0.y);
        }
    }
    float2 acc;
    acc.x = a0.x + a1.x + a2.x + a3.x;
    acc.y = a0.y + a1.y + a2.y + a3.y;
    ((float2*)(out + (size_t)w * 64))[lane] = acc;
}

// ---------------- launch: R10 structure (CSR ∥ GEMM1) ----------------------------
extern "C" void kernel_launch(void* const* d_in, const int* in_sizes, int n_in,
                              void* d_out, int out_size) {
    const float* x  = (const float*)d_in[0];
    const int*   ei = (const int*)  d_in[1];
    const float* W1 = (const float*)d_in[2];
    const float* b1 = (const float*)d_in[3];
    const float* W2 = (const float*)d_in[4];
    const float* b2 = (const float*)d_in[5];

    const int* src = ei;
    const int* dst = ei + N_EDGES;

    float* out_h2 = (float*)d_out;                       // [N, 64]
    float* out_h1 = out_h2 + (size_t)N_NODES * OUT_DIM;  // [N, 128]

    void *p_hh, *p_h2h;
    cudaGetSymbolAddress(&p_hh,  g_hh);
    cudaGetSymbolAddress(&p_h2h, g_h2h);
    __half* hhbuf  = (__half*)p_hh;
    __half* h2hbuf = (__half*)p_h2h;

    static cudaStream_t s2 = nullptr;
    static cudaEvent_t  evFork = nullptr, evJoin = nullptr;
    if (s2 == nullptr) {
        cudaStreamCreateWithFlags(&s2, cudaStreamNonBlocking);
        cudaEventCreateWithFlags(&evFork, cudaEventDisableTiming);
        cudaEventCreateWithFlags(&evJoin, cudaEventDisableTiming);
    }

    const int TB = 256;
    const int nblk_nodes = (N_NODES + TB - 1) / TB;
    const int nblk_edges = (N_EDGES + TB - 1) / TB;

    cudaEventRecord(evFork, 0);
    cudaStreamWaitEvent(s2, evFork, 0);

    // --- stream 0: GEMM1 -> fp16 hbuf ---
    k_gemm<IN_DIM, HID_DIM, 128, 16><<<(N_NODES + 127) / 128, 256>>>(x, W1, hhbuf);

    // --- stream s2: degree + CSR build ---
    k_zero <<<nblk_nodes, TB, 0, s2>>>();
    k_count<<<nblk_edges, TB, 0, s2>>>(dst);
    k_scan1<<<nblk_nodes, TB, 0, s2>>>();
    k_scan2<<<1,          TB, 0, s2>>>(nblk_nodes);
    k_scan3<<<nblk_nodes, TB, 0, s2>>>();
    k_fill <<<nblk_edges, TB, 0, s2>>>(src, dst);

    cudaEventRecord(evJoin, s2);
    cudaStreamWaitEvent(0, evJoin, 0);

    // --- stream 0: pull1 (fp16 gather) -> GEMM2 -> pull2 (fp16 gather) ---
    k_pull128<<<(N_NODES * 32 + TB - 1) / TB, TB>>>(hhbuf, b1, out_h1);
    k_gemm<HID_DIM, OUT_DIM, 128, 16><<<(N_NODES + 127) / 128, 256>>>(out_h1, W2, h2hbuf);
    k_pull64<<<(N_NODES * 32 + TB - 1) / TB, TB>>>(h2hbuf, b2, out_h2);
}

// round 14
// speedup vs baseline: 1.4178x; 1.0283x over previous
#include <cuda_runtime.h>
#include <cuda_fp16.h>
#include <math.h>

#define N_NODES 50000
#define N_EDGES 800000
#define IN_DIM  128
#define HID_DIM 128
#define OUT_DIM 64

typedef unsigned long long ull;

// ---------------- scratch (static device globals; no allocation) ----------------
__device__ float  g_dinv[N_NODES];
__device__ int    g_degi[N_NODES];
__device__ int    g_off [N_NODES + 1];
__device__ int    g_cur [N_NODES];
__device__ int    g_bsum[256];
__device__ int    g_col [N_EDGES];
__device__ __half g_hh  [(size_t)N_NODES * HID_DIM];
__device__ __half g_h2h [(size_t)N_NODES * OUT_DIM];

// ---------------- f32x2 packed math ----------------
__device__ __forceinline__ ull pack2(float lo, float hi) {
    ull r; asm("mov.b64 %0, {%1, %2};" : "=l"(r) : "f"(lo), "f"(hi)); return r;
}
__device__ __forceinline__ ull fma2(ull a, ull b, ull c) {
    ull d; asm("fma.rn.f32x2 %0, %1, %2, %3;" : "=l"(d) : "l"(a), "l"(b), "l"(c)); return d;
}
__device__ __forceinline__ float2 unpack2(ull p) {
    float2 f; asm("mov.b64 {%0, %1}, %2;" : "=f"(f.x), "=f"(f.y) : "l"(p)); return f;
}

// ---------------- degree / norm / CSR build ----------------
__global__ void k_zero() {
    int i = blockIdx.x * blockDim.x + threadIdx.x;
    if (i < N_NODES) g_degi[i] = 0;
}
__global__ void k_count(const int* __restrict__ dst) {
    int e = blockIdx.x * blockDim.x + threadIdx.x;
    if (e < N_EDGES) atomicAdd(&g_degi[dst[e]], 1);
}
__global__ void k_scan1() {
    __shared__ int s[256];
    int i = blockIdx.x * 256 + threadIdx.x;
    int v = (i < N_NODES) ? g_degi[i] : 0;
    if (i < N_NODES) g_dinv[i] = rsqrtf((float)(v + 1));  // +1 self-loop
    s[threadIdx.x] = v;
    __syncthreads();
    for (int d = 1; d < 256; d <<= 1) {
        int t = (threadIdx.x >= d) ? s[threadIdx.x - d] : 0;
        __syncthreads();
        s[threadIdx.x] += t;
        __syncthreads();
    }
    if (i < N_NODES) g_off[i] = s[threadIdx.x] - v;
    if (threadIdx.x == 255) g_bsum[blockIdx.x] = s[255];
}
__global__ void k_scan2(int nblk) {
    __shared__ int s[256];
    int t = threadIdx.x;
    int v = (t < nblk) ? g_bsum[t] : 0;
    s[t] = v;
    __syncthreads();
    for (int d = 1; d < 256; d <<= 1) {
        int u = (t >= d) ? s[t - d] : 0;
        __syncthreads();
        s[t] += u;
        __syncthreads();
    }
    if (t < nblk) g_bsum[t] = s[t] - v;
}
__global__ void k_scan3() {
    int i = blockIdx.x * blockDim.x + threadIdx.x;
    if (i < N_NODES) {
        int o = g_off[i] + g_bsum[i >> 8];
        g_off[i] = o;
        g_cur[i] = o;
    }
    if (i == 0) g_off[N_NODES] = N_EDGES;
}
__global__ void k_fill(const int* __restrict__ src, const int* __restrict__ dst) {
    int e = blockIdx.x * blockDim.x + threadIdx.x;
    if (e < N_EDGES) {
        int p = atomicAdd(&g_cur[dst[e]], 1);
        g_col[p] = src[e];
    }
}

// ---------------- GEMM: f32x2 microtile + double-buffered smem ------------------
template <int K, int N, int RB, int TY>
__global__ void k_gemm(const float* __restrict__ X, const float* __restrict__ W,
                       __half* __restrict__ Y) {
    constexpr int CP = N / 32;
    constexpr int T  = TY * 16;
    __shared__ float xs[2][RB * 33];
    __shared__ float ws[2][32 * N];
    const int tid = threadIdx.x;
    const int tx = tid & 15, ty = tid >> 4;
    const long r0 = (long)blockIdx.x * RB;

    ull acc[8][CP];
#pragma unroll
    for (int r = 0; r < 8; r++)
#pragma unroll
        for (int c = 0; c < CP; c++) acc[r][c] = 0ull;

    // tile loader (stage `b`)
    auto load_tile = [&](int k0, int b) {
        for (int t = tid; t < RB * 8; t += T) {
            int r = t >> 3, q = t & 7;
            long row = r0 + r; if (row >= N_NODES) row = N_NODES - 1;
            float4 v = __ldg((const float4*)(X + row * K + k0) + q);
            float* xp = &xs[b][r * 33 + q * 4];
            xp[0] = v.x; xp[1] = v.y; xp[2] = v.z; xp[3] = v.w;
        }
        const float4* wsrc = (const float4*)(W + (size_t)k0 * N);
        for (int t = tid; t < 8 * N; t += T)
            ((float4*)ws[b])[t] = __ldg(wsrc + t);
    };

    load_tile(0, 0);
    __syncthreads();

    int buf = 0;
    for (int k0 = 0; k0 < K; k0 += 32) {
        if (k0 + 32 < K) load_tile(k0 + 32, buf ^ 1);  // prefetch next stage

        const float* xsb = xs[buf];
        const float* wsb = ws[buf];
#pragma unroll 8
        for (int kk = 0; kk < 32; kk++) {
            ull wv[CP];
#pragma unroll
            for (int c = 0; c < CP; c++)
                wv[c] = *(const ull*)&wsb[kk * N + 2 * tx + 32 * c];
#pragma unroll
            for (int r = 0; r < 8; r++) {
                float xv = xsb[(ty * 8 + r) * 33 + kk];
                ull xx = pack2(xv, xv);
#pragma unroll
                for (int c = 0; c < CP; c++) acc[r][c] = fma2(xx, wv[c], acc[r][c]);
            }
        }
        __syncthreads();
        buf ^= 1;
    }

#pragma unroll
    for (int r = 0; r < 8; r++) {
        long row = r0 + ty * 8 + r;
        if (row < N_NODES) {
#pragma unroll
            for (int c = 0; c < CP; c++) {
                float2 f = unpack2(acc[r][c]);
                *(__half2*)&Y[row * N + 2 * tx + 32 * c] = __floats2half2_rn(f.x, f.y);
            }
        }
    }
}

// ---------------- pull aggregation, C=128: fp16 gather, 2-way (R10 exact) --------
__global__ void k_pull128(const __half* __restrict__ hraw, const float* __restrict__ b,
                          float* __restrict__ out) {
    int w = (blockIdx.x * blockDim.x + threadIdx.x) >> 5;
    if (w >= N_NODES) return;
    int lane = threadIdx.x & 31;
    float din = g_dinv[w];
    uint2 hr = __ldg((const uint2*)(hraw + (size_t)w * 128) + lane);
    float2 h0a = __half22float2(*(__half2*)&hr.x);
    float2 h0b = __half22float2(*(__half2*)&hr.y);
    float4 bv = __ldg((const float4*)b + lane);
    float sl = din * din;
    float4 acc, acc2 = make_float4(0.f, 0.f, 0.f, 0.f);
    acc.x = fmaf(h0a.x, sl, bv.x); acc.y = fmaf(h0a.y, sl, bv.y);
    acc.z = fmaf(h0b.x, sl, bv.z); acc.w = fmaf(h0b.y, sl, bv.w);

    int s0 = g_off[w], s1 = g_off[w + 1];
    for (int j0 = s0; j0 < s1; j0 += 32) {
        int jj = j0 + lane;
        int cc = 0; float nd = 0.0f;
        if (jj < s1) { cc = g_col[jj]; nd = g_dinv[cc]; }
        int cnt = min(32, s1 - j0);
        int i = 0;
        for (; i + 2 <= cnt; i += 2) {
            int   sA = __shfl_sync(0xffffffffu, cc, i);
            float nA = __shfl_sync(0xffffffffu, nd, i) * din;
            int   sB = __shfl_sync(0xffffffffu, cc, i + 1);
            float nB = __shfl_sync(0xffffffffu, nd, i + 1) * din;
            uint2 rA = __ldg((const uint2*)(hraw + (size_t)sA * 128) + lane);
            uint2 rB = __ldg((const uint2*)(hraw + (size_t)sB * 128) + lane);
            float2 a0 = __half22float2(*(__half2*)&rA.x);
            float2 a1 = __half22float2(*(__half2*)&rA.y);
            float2 b0 = __half22float2(*(__half2*)&rB.x);
            float2 b1 = __half22float2(*(__half2*)&rB.y);
            acc.x  = fmaf(a0.x, nA, acc.x);  acc.y  = fmaf(a0.y, nA, acc.y);
            acc.z  = fmaf(a1.x, nA, acc.z);  acc.w  = fmaf(a1.y, nA, acc.w);
            acc2.x = fmaf(b0.x, nB, acc2.x); acc2.y = fmaf(b0.y, nB, acc2.y);
            acc2.z = fmaf(b1.x, nB, acc2.z); acc2.w = fmaf(b1.y, nB, acc2.w);
        }
        if (i < cnt) {
            int   sA = __shfl_sync(0xffffffffu, cc, i);
            float nA = __shfl_sync(0xffffffffu, nd, i) * din;
            uint2 rA = __ldg((const uint2*)(hraw + (size_t)sA * 128) + lane);
            float2 a0 = __half22float2(*(__half2*)&rA.x);
            float2 a1 = __half22float2(*(__half2*)&rA.y);
            acc.x = fmaf(a0.x, nA, acc.x); acc.y = fmaf(a0.y, nA, acc.y);
            acc.z = fmaf(a1.x, nA, acc.z); acc.w = fmaf(a1.y, nA, acc.w);
        }
    }
    acc.x = fmaxf(acc.x + acc2.x, 0.0f); acc.y = fmaxf(acc.y + acc2.y, 0.0f);
    acc.z = fmaxf(acc.z + acc2.z, 0.0f); acc.w = fmaxf(acc.w + acc2.w, 0.0f);
    ((float4*)(out + (size_t)w * 128))[lane] = acc;
}

// ---------------- pull aggregation, C=64: fp16 gather, 2-way (R10 exact) ---------
__global__ void k_pull64(const __half* __restrict__ hraw, const float* __restrict__ b,
                         float* __restrict__ out) {
    int w = (blockIdx.x * blockDim.x + threadIdx.x) >> 5;
    if (w >= N_NODES) return;
    int lane = threadIdx.x & 31;
    float din = g_dinv[w];
    unsigned hr = __ldg((const unsigned*)(hraw + (size_t)w * 64) + lane);
    float2 h0 = __half22float2(*(__half2*)&hr);
    float2 bv = __ldg((const float2*)b + lane);
    float sl = din * din;
    float2 acc, acc2 = make_float2(0.f, 0.f);
    acc.x = fmaf(h0.x, sl, bv.x); acc.y = fmaf(h0.y, sl, bv.y);

    int s0 = g_off[w], s1 = g_off[w + 1];
    for (int j0 = s0; j0 < s1; j0 += 32) {
        int jj = j0 + lane;
        int cc = 0; float nd = 0.0f;
        if (jj < s1) { cc = g_col[jj]; nd = g_dinv[cc]; }
        int cnt = min(32, s1 - j0);
        int i = 0;
        for (; i + 2 <= cnt; i += 2) {
            int   sA = __shfl_sync(0xffffffffu, cc, i);
            float nA = __shfl_sync(0xffffffffu, nd, i) * din;
            int   sB = __shfl_sync(0xffffffffu, cc, i + 1);
            float nB = __shfl_sync(0xffffffffu, nd, i + 1) * din;
            unsigned rA = __ldg((const unsigned*)(hraw + (size_t)sA * 64) + lane);
            unsigned rB = __ldg((const unsigned*)(hraw + (size_t)sB * 64) + lane);
            float2 fA = __half22float2(*(__half2*)&rA);
            float2 fB = __half22float2(*(__half2*)&rB);
            acc.x  = fmaf(fA.x, nA, acc.x);  acc.y  = fmaf(fA.y, nA, acc.y);
            acc2.x = fmaf(fB.x, nB, acc2.x); acc2.y = fmaf(fB.y, nB, acc2.y);
        }
        if (i < cnt) {
            int   sA = __shfl_sync(0xffffffffu, cc, i);
            float nA = __shfl_sync(0xffffffffu, nd, i) * din;
            unsigned rA = __ldg((const unsigned*)(hraw + (size_t)sA * 64) + lane);
            float2 fA = __half22float2(*(__half2*)&rA);
            acc.x = fmaf(fA.x, nA, acc.x); acc.y = fmaf(fA.y, nA, acc.y);
        }
    }
    acc.x += acc2.x; acc.y += acc2.y;
    ((float2*)(out + (size_t)w * 64))[lane] = acc;
}

// ---------------- launch: R10 structure (CSR ∥ GEMM1) ----------------------------
extern "C" void kernel_launch(void* const* d_in, const int* in_sizes, int n_in,
                              void* d_out, int out_size) {
    const float* x  = (const float*)d_in[0];
    const int*   ei = (const int*)  d_in[1];
    const float* W1 = (const float*)d_in[2];
    const float* b1 = (const float*)d_in[3];
    const float* W2 = (const float*)d_in[4];
    const float* b2 = (const float*)d_in[5];

    const int* src = ei;
    const int* dst = ei + N_EDGES;

    float* out_h2 = (float*)d_out;                       // [N, 64]
    float* out_h1 = out_h2 + (size_t)N_NODES * OUT_DIM;  // [N, 128]

    void *p_hh, *p_h2h;
    cudaGetSymbolAddress(&p_hh,  g_hh);
    cudaGetSymbolAddress(&p_h2h, g_h2h);
    __half* hhbuf  = (__half*)p_hh;
    __half* h2hbuf = (__half*)p_h2h;

    static cudaStream_t s2 = nullptr;
    static cudaEvent_t  evFork = nullptr, evJoin = nullptr;
    if (s2 == nullptr) {
        cudaStreamCreateWithFlags(&s2, cudaStreamNonBlocking);
        cudaEventCreateWithFlags(&evFork, cudaEventDisableTiming);
        cudaEventCreateWithFlags(&evJoin, cudaEventDisableTiming);
    }

    const int TB = 256;
    const int nblk_nodes = (N_NODES + TB - 1) / TB;
    const int nblk_edges = (N_EDGES + TB - 1) / TB;

    cudaEventRecord(evFork, 0);
    cudaStreamWaitEvent(s2, evFork, 0);

    // --- stream 0: GEMM1 (double-buffered) -> fp16 hbuf ---
    k_gemm<IN_DIM, HID_DIM, 128, 16><<<(N_NODES + 127) / 128, 256>>>(x, W1, hhbuf);

    // --- stream s2: degree + CSR build ---
    k_zero <<<nblk_nodes, TB, 0, s2>>>();
    k_count<<<nblk_edges, TB, 0, s2>>>(dst);
    k_scan1<<<nblk_nodes, TB, 0, s2>>>();
    k_scan2<<<1,          TB, 0, s2>>>(nblk_nodes);
    k_scan3<<<nblk_nodes, TB, 0, s2>>>();
    k_fill <<<nblk_edges, TB, 0, s2>>>(src, dst);

    cudaEventRecord(evJoin, s2);
    cudaStreamWaitEvent(0, evJoin, 0);

    // --- stream 0: pull1 -> GEMM2 (double-buffered) -> pull2 ---
    k_pull128<<<(N_NODES * 32 + TB - 1) / TB, TB>>>(hhbuf, b1, out_h1);
    k_gemm<HID_DIM, OUT_DIM, 128, 16><<<(N_NODES + 127) / 128, 256>>>(out_h1, W2, h2hbuf);
    k_pull64<<<(N_NODES * 32 + TB - 1) / TB, TB>>>(h2hbuf, b2, out_h2);
}